// round 8
// baseline (speedup 1.0000x reference)
#include <cuda_runtime.h>
#include <cstdint>

#define IN_F   4096
#define OUT_F  4096
#define TOKENS 8192
#define NGRP   32          // K groups of 128

#define BM 128
#define BN 128

// smem stage layout: 160B-padded rows (40 words -> conflict-free LDS.64)
#define ROWB   160
#define SA_HI  0
#define SA_LO  20480
#define SB_OFF 40960
#define SSC    61440
#define STG_SZ 61952
#define SMEM_TOTAL (3 * STG_SZ)     // 185856

// GEMM-ready gmem images (frag-order permuted within each 32B k-block)
__device__ uint8_t g_A_hi[(size_t)TOKENS * IN_F];
__device__ uint8_t g_A_lo[(size_t)TOKENS * IN_F];
__device__ uint8_t g_B[(size_t)OUT_F * IN_F];
__device__ float   g_alpha[TOKENS];

__device__ __forceinline__ uint32_t smem_u32(const void* p) {
    return (uint32_t)__cvta_generic_to_shared(p);
}
__device__ __forceinline__ void cp16(uint32_t saddr, const void* g) {
    asm volatile("cp.async.cg.shared.global [%0], [%1], 16;\n" :: "r"(saddr), "l"(g));
}
__device__ __forceinline__ void lds64(uint32_t& x, uint32_t& y, uint32_t a) {
    asm volatile("ld.shared.v2.u32 {%0,%1}, [%2];" : "=r"(x), "=r"(y) : "r"(a));
}
__device__ __forceinline__ void lds64f(float& x, float& y, uint32_t a) {
    asm volatile("ld.shared.v2.f32 {%0,%1}, [%2];" : "=f"(x), "=f"(y) : "r"(a));
}

// m16n8k32 integer mma
__device__ __forceinline__ void imma_s8(int* d, const uint32_t* a, const uint32_t* b, bool acc) {
    if (acc)
        asm volatile("mma.sync.aligned.m16n8k32.row.col.s32.s8.s8.s32 "
                     "{%0,%1,%2,%3},{%4,%5,%6,%7},{%8,%9},{%0,%1,%2,%3};"
                     : "+r"(d[0]), "+r"(d[1]), "+r"(d[2]), "+r"(d[3])
                     : "r"(a[0]), "r"(a[1]), "r"(a[2]), "r"(a[3]), "r"(b[0]), "r"(b[1]));
    else
        asm volatile("mma.sync.aligned.m16n8k32.row.col.s32.s8.s8.s32 "
                     "{%0,%1,%2,%3},{%4,%5,%6,%7},{%8,%9},{%10,%10,%10,%10};"
                     : "=r"(d[0]), "=r"(d[1]), "=r"(d[2]), "=r"(d[3])
                     : "r"(a[0]), "r"(a[1]), "r"(a[2]), "r"(a[3]), "r"(b[0]), "r"(b[1]),
                       "r"(0));
}
__device__ __forceinline__ void imma_u8(int* d, const uint32_t* a, const uint32_t* b, bool acc) {
    if (acc)
        asm volatile("mma.sync.aligned.m16n8k32.row.col.s32.u8.s8.s32 "
                     "{%0,%1,%2,%3},{%4,%5,%6,%7},{%8,%9},{%0,%1,%2,%3};"
                     : "+r"(d[0]), "+r"(d[1]), "+r"(d[2]), "+r"(d[3])
                     : "r"(a[0]), "r"(a[1]), "r"(a[2]), "r"(a[3]), "r"(b[0]), "r"(b[1]));
    else
        asm volatile("mma.sync.aligned.m16n8k32.row.col.s32.u8.s8.s32 "
                     "{%0,%1,%2,%3},{%4,%5,%6,%7},{%8,%9},{%10,%10,%10,%10};"
                     : "=r"(d[0]), "=r"(d[1]), "=r"(d[2]), "=r"(d[3])
                     : "r"(a[0]), "r"(a[1]), "r"(a[2]), "r"(a[3]), "r"(b[0]), "r"(b[1]),
                       "r"(0));
}

// frag-order permutation of a 4-aligned k index within its 32B block
__device__ __forceinline__ int perm4(int k) {
    int blk = k & ~31, r = k & 31;
    return blk + (((r & 15) >> 2) << 3) + ((r >> 4) << 2);
}

// ---------------------------------------------------------------------------
// Prepass 1: per-token absmax quantize x -> hi/lo s8 planes (permuted layout)
// one block per token row, 256 threads, 16 k each
// ---------------------------------------------------------------------------
__global__ void __launch_bounds__(256) quant_kernel(const float* __restrict__ x) {
    const int m = blockIdx.x, t = threadIdx.x;
    const float4* xr = (const float4*)(x + (size_t)m * IN_F);
    float4 v[4];
    float mx = 0.0f;
#pragma unroll
    for (int i = 0; i < 4; i++) {
        v[i] = xr[t + 256 * i];
        mx = fmaxf(mx, fmaxf(fmaxf(fabsf(v[i].x), fabsf(v[i].y)),
                             fmaxf(fabsf(v[i].z), fabsf(v[i].w))));
    }
#pragma unroll
    for (int o = 16; o > 0; o >>= 1) mx = fmaxf(mx, __shfl_xor_sync(0xffffffffu, mx, o));
    __shared__ float red[8];
    __shared__ float s_ainv;
    if ((t & 31) == 0) red[t >> 5] = mx;
    __syncthreads();
    if (t == 0) {
        float r = red[0];
#pragma unroll
        for (int i = 1; i < 8; i++) r = fmaxf(r, red[i]);
        g_alpha[m] = r * (1.0f / 32639.0f);
        s_ainv = r > 0.0f ? 32639.0f / r : 0.0f;
    }
    __syncthreads();
    const float ainv = s_ainv;
    uint8_t* ph = g_A_hi + (size_t)m * IN_F;
    uint8_t* pl = g_A_lo + (size_t)m * IN_F;
#pragma unroll
    for (int i = 0; i < 4; i++) {
        int kb = (t + 256 * i) * 4;
        int q0 = __float2int_rn(v[i].x * ainv);
        int q1 = __float2int_rn(v[i].y * ainv);
        int q2 = __float2int_rn(v[i].z * ainv);
        int q3 = __float2int_rn(v[i].w * ainv);
        uint32_t hi = ((uint32_t)((q0 >> 8) & 255))       | ((uint32_t)((q1 >> 8) & 255) << 8)
                    | ((uint32_t)((q2 >> 8) & 255) << 16) | ((uint32_t)((q3 >> 8) & 255) << 24);
        uint32_t lo = ((uint32_t)(q0 & 255))       | ((uint32_t)(q1 & 255) << 8)
                    | ((uint32_t)(q2 & 255) << 16) | ((uint32_t)(q3 & 255) << 24);
        int p = perm4(kb);
        *(uint32_t*)(ph + p) = hi;
        *(uint32_t*)(pl + p) = lo;
    }
}

// ---------------------------------------------------------------------------
// Prepass 2: dequant weights to s8 (w - z), permuted n-major layout g_B[n][k]
// block: (n chunk of 256, k block of 32)
// ---------------------------------------------------------------------------
__global__ void __launch_bounds__(256) dequantb_kernel(const int* __restrict__ qw,
                                                       const int* __restrict__ qz) {
    const int n   = blockIdx.x * 256 + threadIdx.x;
    const int blk = blockIdx.y * 32;
    const int g   = blk >> 7;
    uint32_t zw = (uint32_t)qz[g * (OUT_F / 8) + (n >> 3)];
    int z = (int)((zw >> ((n & 7) * 4)) & 15u) + 1;
    uint32_t w[4];
#pragma unroll
    for (int j = 0; j < 4; j++)
        w[j] = (uint32_t)qw[(size_t)(blk / 8 + j) * OUT_F + n];
    uint8_t* dst = g_B + (size_t)n * IN_F + blk;
#pragma unroll
    for (int jj = 0; jj < 4; jj++) {
        int j  = jj >> 1;
        int i0 = (jj & 1) * 4;
        uint32_t pa = 0, pb = 0;
#pragma unroll
        for (int tt = 0; tt < 4; tt++) {
            int va = (int)((w[j]     >> (4 * (i0 + tt))) & 15u) - z;   // k = blk+jj*4+tt
            int vb = (int)((w[j + 2] >> (4 * (i0 + tt))) & 15u) - z;   // k = blk+16+jj*4+tt
            pa |= (uint32_t)(va & 255) << (8 * tt);
            pb |= (uint32_t)(vb & 255) << (8 * tt);
        }
        uint2 u; u.x = pa; u.y = pb;
        *(uint2*)(dst + jj * 8) = u;        // positions jj*8 .. jj*8+7 (frag order)
    }
}

// ---------------------------------------------------------------------------
// GEMM: out[M,N] = alpha_m * sum_g s_g[n]*(256*Hi_g + Lo_g) + bias
// CTA 128x128, 256 threads, warps 4(m) x 2(n), warp tile 32x64.
// 3-stage cp.async ring over 32 groups (K=128 each = 4 k32 steps).
// ---------------------------------------------------------------------------
__global__ void __launch_bounds__(256, 1)
gemm_kernel(const float* __restrict__ scales, const float* __restrict__ bias,
            float* __restrict__ out) {
    extern __shared__ __align__(16) char smem[];
    const uint32_t sb = smem_u32(smem);
    const int tid  = threadIdx.x;
    const int wid  = tid >> 5;
    const int lane = tid & 31;
    const int wm   = wid & 3;       // m-warp 0..3
    const int wn   = wid >> 2;      // n-warp 0..1
    const int m0   = blockIdx.y * BM;
    const int n0   = blockIdx.x * BN;

    float facc[2][8][4];
#pragma unroll
    for (int mi = 0; mi < 2; mi++)
#pragma unroll
        for (int ni = 0; ni < 8; ni++)
#pragma unroll
            for (int j = 0; j < 4; j++) facc[mi][ni][j] = 0.0f;

    auto fill = [&](int g) {
        uint32_t st = sb + (uint32_t)(g % 3) * STG_SZ;
        const uint8_t* ah = g_A_hi + (size_t)m0 * IN_F + g * 128;
        const uint8_t* al = g_A_lo + (size_t)m0 * IN_F + g * 128;
        const uint8_t* bg = g_B    + (size_t)n0 * IN_F + g * 128;
#pragma unroll
        for (int j = 0; j < 4; j++) {
            int c = tid + 256 * j;
            int row = c >> 3, col = (c & 7) * 16;
            size_t go = (size_t)row * IN_F + col;
            uint32_t so = (uint32_t)row * ROWB + col;
            cp16(st + SA_HI  + so, ah + go);
            cp16(st + SA_LO  + so, al + go);
            cp16(st + SB_OFF + so, bg + go);
        }
        if (tid < 32)
            cp16(st + SSC + tid * 16, scales + (size_t)g * OUT_F + n0 + tid * 4);
    };

    fill(0);
    asm volatile("cp.async.commit_group;\n" ::: "memory");
    fill(1);
    asm volatile("cp.async.commit_group;\n" ::: "memory");

    for (int g = 0; g < NGRP; g++) {
        asm volatile("cp.async.wait_group 1;\n" ::: "memory");
        __syncthreads();
        if (g + 2 < NGRP) fill(g + 2);
        asm volatile("cp.async.commit_group;\n" ::: "memory");

        const uint32_t st = sb + (uint32_t)(g % 3) * STG_SZ;

        // group scales (2 cols per ni)
        float2 sc[8];
        {
            uint32_t scb = st + SSC + (uint32_t)(wn * 64 + (lane & 3) * 2) * 4;
#pragma unroll
            for (int ni = 0; ni < 8; ni++) lds64f(sc[ni].x, sc[ni].y, scb + ni * 32);
        }

        const uint32_t a_row = (uint32_t)(wm * 32 + (lane >> 2)) * ROWB + (lane & 3) * 8;
        const uint32_t b_row = (uint32_t)(wn * 64 + (lane >> 2)) * ROWB + (lane & 3) * 8;

        int ia[2][8][4];

        // ---- hi pass (s8) ----
#pragma unroll
        for (int ks = 0; ks < 4; ks++) {
            uint32_t a[2][4], b[8][2];
#pragma unroll
            for (int mi = 0; mi < 2; mi++) {
                uint32_t r0 = st + SA_HI + a_row + (uint32_t)(mi * 16) * ROWB + ks * 32;
                lds64(a[mi][0], a[mi][2], r0);
                lds64(a[mi][1], a[mi][3], r0 + 8 * ROWB);
            }
#pragma unroll
            for (int ni = 0; ni < 8; ni++)
                lds64(b[ni][0], b[ni][1],
                      st + SB_OFF + b_row + (uint32_t)(ni * 8) * ROWB + ks * 32);
#pragma unroll
            for (int mi = 0; mi < 2; mi++)
#pragma unroll
                for (int ni = 0; ni < 8; ni++)
                    imma_s8(ia[mi][ni], a[mi], b[ni], ks > 0);
        }
        // fold hi: facc += (256*s) * Ihi
#pragma unroll
        for (int ni = 0; ni < 8; ni++) {
            float sx = sc[ni].x * 256.0f, sy = sc[ni].y * 256.0f;
#pragma unroll
            for (int mi = 0; mi < 2; mi++) {
                facc[mi][ni][0] += sx * (float)ia[mi][ni][0];
                facc[mi][ni][1] += sy * (float)ia[mi][ni][1];
                facc[mi][ni][2] += sx * (float)ia[mi][ni][2];
                facc[mi][ni][3] += sy * (float)ia[mi][ni][3];
            }
        }

        // ---- lo pass (u8) ----
#pragma unroll
        for (int ks = 0; ks < 4; ks++) {
            uint32_t a[2][4], b[8][2];
#pragma unroll
            for (int mi = 0; mi < 2; mi++) {
                uint32_t r0 = st + SA_LO + a_row + (uint32_t)(mi * 16) * ROWB + ks * 32;
                lds64(a[mi][0], a[mi][2], r0);
                lds64(a[mi][1], a[mi][3], r0 + 8 * ROWB);
            }
#pragma unroll
            for (int ni = 0; ni < 8; ni++)
                lds64(b[ni][0], b[ni][1],
                      st + SB_OFF + b_row + (uint32_t)(ni * 8) * ROWB + ks * 32);
#pragma unroll
            for (int mi = 0; mi < 2; mi++)
#pragma unroll
                for (int ni = 0; ni < 8; ni++)
                    imma_u8(ia[mi][ni], a[mi], b[ni], ks > 0);
        }
        // fold lo: facc += s * Ilo
#pragma unroll
        for (int ni = 0; ni < 8; ni++) {
            float sx = sc[ni].x, sy = sc[ni].y;
#pragma unroll
            for (int mi = 0; mi < 2; mi++) {
                facc[mi][ni][0] += sx * (float)ia[mi][ni][0];
                facc[mi][ni][1] += sy * (float)ia[mi][ni][1];
                facc[mi][ni][2] += sx * (float)ia[mi][ni][2];
                facc[mi][ni][3] += sy * (float)ia[mi][ni][3];
            }
        }
    }

    // ---- epilogue: alpha_m * acc + bias ----
#pragma unroll
    for (int mi = 0; mi < 2; mi++) {
        int r0 = m0 + wm * 32 + mi * 16 + (lane >> 2);
        float al0 = g_alpha[r0], al1 = g_alpha[r0 + 8];
#pragma unroll
        for (int ni = 0; ni < 8; ni++) {
            int c = n0 + wn * 64 + ni * 8 + (lane & 3) * 2;
            float2 bv = *(const float2*)(bias + c);
            float2 v0, v1;
            v0.x = al0 * facc[mi][ni][0] + bv.x;
            v0.y = al0 * facc[mi][ni][1] + bv.y;
            v1.x = al1 * facc[mi][ni][2] + bv.x;
            v1.y = al1 * facc[mi][ni][3] + bv.y;
            *(float2*)(out + (size_t)r0 * OUT_F + c)       = v0;
            *(float2*)(out + (size_t)(r0 + 8) * OUT_F + c) = v1;
        }
    }
}

// ---------------------------------------------------------------------------
// Launch.  inputs: x, qweight, qzeros, scales, g_idx, bias
// ---------------------------------------------------------------------------
extern "C" void kernel_launch(void* const* d_in, const int* in_sizes, int n_in,
                              void* d_out, int out_size) {
    const float* x       = (const float*)d_in[0];
    const int*   qweight = (const int*)d_in[1];
    const int*   qzeros  = (const int*)d_in[2];
    const float* scales  = (const float*)d_in[3];
    const float* bias    = (const float*)d_in[5];
    float*       out     = (float*)d_out;

    quant_kernel<<<TOKENS, 256>>>(x);
    dequantb_kernel<<<dim3(OUT_F / 256, IN_F / 32), 256>>>(qweight, qzeros);

    cudaFuncSetAttribute(gemm_kernel, cudaFuncAttributeMaxDynamicSharedMemorySize,
                         SMEM_TOTAL);
    dim3 grid(OUT_F / BN, TOKENS / BM);
    gemm_kernel<<<grid, 256, SMEM_TOTAL>>>(scales, bias, out);
}

// round 9
// speedup vs baseline: 1.0024x; 1.0024x over previous
#include <cuda_runtime.h>
#include <cstdint>

#define IN_F   4096
#define OUT_F  4096
#define TOKENS 8192
#define NGRP   32          // K groups of 128

#define BM 128
#define BN 128

// smem stage layout: 160B-padded rows (conflict-free LDS.64 per half-warp phase)
#define ROWB   160
#define SA_HI  0
#define SA_LO  20480
#define SB_OFF 40960
#define SSC    61440
#define STG_SZ 61952
#define SMEM_TOTAL (3 * STG_SZ)     // 185856

// GEMM-ready gmem images (frag-order permuted within each 32B k-block)
__device__ uint8_t g_A_hi[(size_t)TOKENS * IN_F];
__device__ uint8_t g_A_lo[(size_t)TOKENS * IN_F];
__device__ uint8_t g_B[(size_t)OUT_F * IN_F];
__device__ float   g_alpha[TOKENS];

__device__ __forceinline__ uint32_t smem_u32(const void* p) {
    return (uint32_t)__cvta_generic_to_shared(p);
}
__device__ __forceinline__ void cp16(uint32_t saddr, const void* g) {
    asm volatile("cp.async.cg.shared.global [%0], [%1], 16;\n" :: "r"(saddr), "l"(g));
}
__device__ __forceinline__ void lds64(uint32_t& x, uint32_t& y, uint32_t a) {
    asm volatile("ld.shared.v2.u32 {%0,%1}, [%2];" : "=r"(x), "=r"(y) : "r"(a));
}
__device__ __forceinline__ void lds64f(float& x, float& y, uint32_t a) {
    asm volatile("ld.shared.v2.f32 {%0,%1}, [%2];" : "=f"(x), "=f"(y) : "r"(a));
}

// exact int->float for |v| < 2^22 without I2F (IADD + FSUB, both rt-2 pipes)
#define MAGIC_I 0x4B400000
#define MAGIC_F 12582912.0f

// m16n8k32 integer mma
__device__ __forceinline__ void imma_s8(int* d, const uint32_t* a, const uint32_t* b, bool acc) {
    if (acc)
        asm volatile("mma.sync.aligned.m16n8k32.row.col.s32.s8.s8.s32 "
                     "{%0,%1,%2,%3},{%4,%5,%6,%7},{%8,%9},{%0,%1,%2,%3};"
                     : "+r"(d[0]), "+r"(d[1]), "+r"(d[2]), "+r"(d[3])
                     : "r"(a[0]), "r"(a[1]), "r"(a[2]), "r"(a[3]), "r"(b[0]), "r"(b[1]));
    else
        asm volatile("mma.sync.aligned.m16n8k32.row.col.s32.s8.s8.s32 "
                     "{%0,%1,%2,%3},{%4,%5,%6,%7},{%8,%9},{%10,%10,%10,%10};"
                     : "=r"(d[0]), "=r"(d[1]), "=r"(d[2]), "=r"(d[3])
                     : "r"(a[0]), "r"(a[1]), "r"(a[2]), "r"(a[3]), "r"(b[0]), "r"(b[1]),
                       "r"(0));
}
__device__ __forceinline__ void imma_u8(int* d, const uint32_t* a, const uint32_t* b, bool acc) {
    if (acc)
        asm volatile("mma.sync.aligned.m16n8k32.row.col.s32.u8.s8.s32 "
                     "{%0,%1,%2,%3},{%4,%5,%6,%7},{%8,%9},{%0,%1,%2,%3};"
                     : "+r"(d[0]), "+r"(d[1]), "+r"(d[2]), "+r"(d[3])
                     : "r"(a[0]), "r"(a[1]), "r"(a[2]), "r"(a[3]), "r"(b[0]), "r"(b[1]));
    else
        asm volatile("mma.sync.aligned.m16n8k32.row.col.s32.u8.s8.s32 "
                     "{%0,%1,%2,%3},{%4,%5,%6,%7},{%8,%9},{%10,%10,%10,%10};"
                     : "=r"(d[0]), "=r"(d[1]), "=r"(d[2]), "=r"(d[3])
                     : "r"(a[0]), "r"(a[1]), "r"(a[2]), "r"(a[3]), "r"(b[0]), "r"(b[1]),
                       "r"(0));
}

// frag-order permutation of a 4-aligned k index within its 32B block
__device__ __forceinline__ int perm4(int k) {
    int blk = k & ~31, r = k & 31;
    return blk + (((r & 15) >> 2) << 3) + ((r >> 4) << 2);
}

// ---------------------------------------------------------------------------
// Prepass 1: per-token absmax quantize x -> hi/lo s8 planes (permuted layout)
// ---------------------------------------------------------------------------
__global__ void __launch_bounds__(256) quant_kernel(const float* __restrict__ x) {
    const int m = blockIdx.x, t = threadIdx.x;
    const float4* xr = (const float4*)(x + (size_t)m * IN_F);
    float4 v[4];
    float mx = 0.0f;
#pragma unroll
    for (int i = 0; i < 4; i++) {
        v[i] = xr[t + 256 * i];
        mx = fmaxf(mx, fmaxf(fmaxf(fabsf(v[i].x), fabsf(v[i].y)),
                             fmaxf(fabsf(v[i].z), fabsf(v[i].w))));
    }
#pragma unroll
    for (int o = 16; o > 0; o >>= 1) mx = fmaxf(mx, __shfl_xor_sync(0xffffffffu, mx, o));
    __shared__ float red[8];
    __shared__ float s_ainv;
    if ((t & 31) == 0) red[t >> 5] = mx;
    __syncthreads();
    if (t == 0) {
        float r = red[0];
#pragma unroll
        for (int i = 1; i < 8; i++) r = fmaxf(r, red[i]);
        g_alpha[m] = r * (1.0f / 32639.0f);
        s_ainv = r > 0.0f ? 32639.0f / r : 0.0f;
    }
    __syncthreads();
    const float ainv = s_ainv;
    uint8_t* ph = g_A_hi + (size_t)m * IN_F;
    uint8_t* pl = g_A_lo + (size_t)m * IN_F;
#pragma unroll
    for (int i = 0; i < 4; i++) {
        int kb = (t + 256 * i) * 4;
        int q0 = __float2int_rn(v[i].x * ainv);
        int q1 = __float2int_rn(v[i].y * ainv);
        int q2 = __float2int_rn(v[i].z * ainv);
        int q3 = __float2int_rn(v[i].w * ainv);
        uint32_t hi = ((uint32_t)((q0 >> 8) & 255))       | ((uint32_t)((q1 >> 8) & 255) << 8)
                    | ((uint32_t)((q2 >> 8) & 255) << 16) | ((uint32_t)((q3 >> 8) & 255) << 24);
        uint32_t lo = ((uint32_t)(q0 & 255))       | ((uint32_t)(q1 & 255) << 8)
                    | ((uint32_t)(q2 & 255) << 16) | ((uint32_t)(q3 & 255) << 24);
        int p = perm4(kb);
        *(uint32_t*)(ph + p) = hi;
        *(uint32_t*)(pl + p) = lo;
    }
}

// ---------------------------------------------------------------------------
// Prepass 2: dequant weights to s8 (w - z), permuted n-major layout g_B[n][k]
// ---------------------------------------------------------------------------
__global__ void __launch_bounds__(256) dequantb_kernel(const int* __restrict__ qw,
                                                       const int* __restrict__ qz) {
    const int n   = blockIdx.x * 256 + threadIdx.x;
    const int blk = blockIdx.y * 32;
    const int g   = blk >> 7;
    uint32_t zw = (uint32_t)qz[g * (OUT_F / 8) + (n >> 3)];
    int z = (int)((zw >> ((n & 7) * 4)) & 15u) + 1;
    uint32_t w[4];
#pragma unroll
    for (int j = 0; j < 4; j++)
        w[j] = (uint32_t)qw[(size_t)(blk / 8 + j) * OUT_F + n];
    uint8_t* dst = g_B + (size_t)n * IN_F + blk;
#pragma unroll
    for (int jj = 0; jj < 4; jj++) {
        int j  = jj >> 1;
        int i0 = (jj & 1) * 4;
        uint32_t pa = 0, pb = 0;
#pragma unroll
        for (int tt = 0; tt < 4; tt++) {
            int va = (int)((w[j]     >> (4 * (i0 + tt))) & 15u) - z;
            int vb = (int)((w[j + 2] >> (4 * (i0 + tt))) & 15u) - z;
            pa |= (uint32_t)(va & 255) << (8 * tt);
            pb |= (uint32_t)(vb & 255) << (8 * tt);
        }
        uint2 u; u.x = pa; u.y = pb;
        *(uint2*)(dst + jj * 8) = u;
    }
}

// ---------------------------------------------------------------------------
// GEMM: out = alpha_m * sum_g s_g[n]*(256*Hi_g + Lo_g) + bias
// CTA 128x128, 512 threads, warps 4(m) x 4(n), warp tile 32x32.
// 3-stage cp.async ring over 32 groups.
// ---------------------------------------------------------------------------
__global__ void __launch_bounds__(512, 1)
gemm_kernel(const float* __restrict__ scales, const float* __restrict__ bias,
            float* __restrict__ out) {
    extern __shared__ __align__(16) char smem[];
    const uint32_t sb = smem_u32(smem);
    const int tid  = threadIdx.x;
    const int wid  = tid >> 5;
    const int lane = tid & 31;
    const int wm   = wid & 3;       // m-warp 0..3
    const int wn   = wid >> 2;      // n-warp 0..3
    const int m0   = blockIdx.y * BM;
    const int n0   = blockIdx.x * BN;

    float facc[2][4][4];
#pragma unroll
    for (int mi = 0; mi < 2; mi++)
#pragma unroll
        for (int ni = 0; ni < 4; ni++)
#pragma unroll
            for (int j = 0; j < 4; j++) facc[mi][ni][j] = 0.0f;

    auto fill = [&](int g) {
        uint32_t st = sb + (uint32_t)(g % 3) * STG_SZ;
        const uint8_t* ah = g_A_hi + (size_t)m0 * IN_F + g * 128;
        const uint8_t* al = g_A_lo + (size_t)m0 * IN_F + g * 128;
        const uint8_t* bg = g_B    + (size_t)n0 * IN_F + g * 128;
#pragma unroll
        for (int j = 0; j < 2; j++) {
            int c = tid + 512 * j;
            int row = c >> 3, col = (c & 7) * 16;
            size_t go = (size_t)row * IN_F + col;
            uint32_t so = (uint32_t)row * ROWB + col;
            cp16(st + SA_HI  + so, ah + go);
            cp16(st + SA_LO  + so, al + go);
            cp16(st + SB_OFF + so, bg + go);
        }
        if (tid < 32)
            cp16(st + SSC + tid * 16, scales + (size_t)g * OUT_F + n0 + tid * 4);
    };

    fill(0);
    asm volatile("cp.async.commit_group;\n" ::: "memory");
    fill(1);
    asm volatile("cp.async.commit_group;\n" ::: "memory");

    const uint32_t a_row = (uint32_t)(wm * 32 + (lane >> 2)) * ROWB + (lane & 3) * 8;
    const uint32_t b_row = (uint32_t)(wn * 32 + (lane >> 2)) * ROWB + (lane & 3) * 8;

    for (int g = 0; g < NGRP; g++) {
        asm volatile("cp.async.wait_group 1;\n" ::: "memory");
        __syncthreads();
        if (g + 2 < NGRP) fill(g + 2);
        asm volatile("cp.async.commit_group;\n" ::: "memory");

        const uint32_t st = sb + (uint32_t)(g % 3) * STG_SZ;

        // group scales: 2 cols per ni (this thread's output columns)
        float2 sc[4];
        {
            uint32_t scb = st + SSC + (uint32_t)(wn * 32 + (lane & 3) * 2) * 4;
#pragma unroll
            for (int ni = 0; ni < 4; ni++) lds64f(sc[ni].x, sc[ni].y, scb + ni * 32);
        }

        int ia[2][4][4];

        // ---- hi pass (s8), fold with 256*s ----
#pragma unroll
        for (int ks = 0; ks < 4; ks++) {
            uint32_t a[2][4], b[4][2];
#pragma unroll
            for (int mi = 0; mi < 2; mi++) {
                uint32_t r0 = st + SA_HI + a_row + (uint32_t)(mi * 16) * ROWB + ks * 32;
                lds64(a[mi][0], a[mi][2], r0);
                lds64(a[mi][1], a[mi][3], r0 + 8 * ROWB);
            }
#pragma unroll
            for (int ni = 0; ni < 4; ni++)
                lds64(b[ni][0], b[ni][1],
                      st + SB_OFF + b_row + (uint32_t)(ni * 8) * ROWB + ks * 32);
#pragma unroll
            for (int mi = 0; mi < 2; mi++)
#pragma unroll
                for (int ni = 0; ni < 4; ni++)
                    imma_s8(ia[mi][ni], a[mi], b[ni], ks > 0);
        }
#pragma unroll
        for (int ni = 0; ni < 4; ni++) {
            float sx = sc[ni].x * 256.0f, sy = sc[ni].y * 256.0f;
#pragma unroll
            for (int mi = 0; mi < 2; mi++) {
#pragma unroll
                for (int j = 0; j < 4; j++) {
                    float f = __int_as_float(ia[mi][ni][j] + MAGIC_I) - MAGIC_F; // exact
                    facc[mi][ni][j] = fmaf((j & 1) ? sy : sx, f, facc[mi][ni][j]);
                }
            }
        }

        // ---- lo pass (u8), fold with s ----
#pragma unroll
        for (int ks = 0; ks < 4; ks++) {
            uint32_t a[2][4], b[4][2];
#pragma unroll
            for (int mi = 0; mi < 2; mi++) {
                uint32_t r0 = st + SA_LO + a_row + (uint32_t)(mi * 16) * ROWB + ks * 32;
                lds64(a[mi][0], a[mi][2], r0);
                lds64(a[mi][1], a[mi][3], r0 + 8 * ROWB);
            }
#pragma unroll
            for (int ni = 0; ni < 4; ni++)
                lds64(b[ni][0], b[ni][1],
                      st + SB_OFF + b_row + (uint32_t)(ni * 8) * ROWB + ks * 32);
#pragma unroll
            for (int mi = 0; mi < 2; mi++)
#pragma unroll
                for (int ni = 0; ni < 4; ni++)
                    imma_u8(ia[mi][ni], a[mi], b[ni], ks > 0);
        }
#pragma unroll
        for (int ni = 0; ni < 4; ni++) {
            float sx = sc[ni].x, sy = sc[ni].y;
#pragma unroll
            for (int mi = 0; mi < 2; mi++) {
#pragma unroll
                for (int j = 0; j < 4; j++) {
                    float f = __int_as_float(ia[mi][ni][j] + MAGIC_I) - MAGIC_F; // exact
                    facc[mi][ni][j] = fmaf((j & 1) ? sy : sx, f, facc[mi][ni][j]);
                }
            }
        }
    }

    // ---- epilogue: alpha_m * acc + bias ----
#pragma unroll
    for (int mi = 0; mi < 2; mi++) {
        int r0 = m0 + wm * 32 + mi * 16 + (lane >> 2);
        float al0 = g_alpha[r0], al1 = g_alpha[r0 + 8];
#pragma unroll
        for (int ni = 0; ni < 4; ni++) {
            int c = n0 + wn * 32 + ni * 8 + (lane & 3) * 2;
            float2 bv = *(const float2*)(bias + c);
            float2 v0, v1;
            v0.x = al0 * facc[mi][ni][0] + bv.x;
            v0.y = al0 * facc[mi][ni][1] + bv.y;
            v1.x = al1 * facc[mi][ni][2] + bv.x;
            v1.y = al1 * facc[mi][ni][3] + bv.y;
            *(float2*)(out + (size_t)r0 * OUT_F + c)       = v0;
            *(float2*)(out + (size_t)(r0 + 8) * OUT_F + c) = v1;
        }
    }
}

// ---------------------------------------------------------------------------
// Launch.  inputs: x, qweight, qzeros, scales, g_idx, bias
// ---------------------------------------------------------------------------
extern "C" void kernel_launch(void* const* d_in, const int* in_sizes, int n_in,
                              void* d_out, int out_size) {
    const float* x       = (const float*)d_in[0];
    const int*   qweight = (const int*)d_in[1];
    const int*   qzeros  = (const int*)d_in[2];
    const float* scales  = (const float*)d_in[3];
    const float* bias    = (const float*)d_in[5];
    float*       out     = (float*)d_out;

    quant_kernel<<<TOKENS, 256>>>(x);
    dequantb_kernel<<<dim3(OUT_F / 256, IN_F / 32), 256>>>(qweight, qzeros);

    cudaFuncSetAttribute(gemm_kernel, cudaFuncAttributeMaxDynamicSharedMemorySize,
                         SMEM_TOTAL);
    dim3 grid(OUT_F / BN, TOKENS / BM);
    gemm_kernel<<<grid, 512, SMEM_TOTAL>>>(scales, bias, out);
}

// round 10
// speedup vs baseline: 4.9962x; 4.9840x over previous
#include <cuda_runtime.h>
#include <cuda_fp16.h>
#include <cstdint>

#define IN_F   4096
#define OUT_F  4096
#define TOKENS 8192

#define BM 128
#define BN 256
#define BK 32
#define NKI  (IN_F / BK)    // 128
#define KB16 (IN_F / 16)    // 256 k16-blocks along K

// fragment-major fp16 images: one 512B block per (16 x 16) tile, lane-major
__device__ __align__(16) uint8_t g_Ah[(size_t)TOKENS * IN_F * 2];  // 64 MB
__device__ __align__(16) uint8_t g_Bh[(size_t)OUT_F * IN_F * 2];   // 32 MB

__device__ __forceinline__ uint32_t smem_u32(const void* p) {
    return (uint32_t)__cvta_generic_to_shared(p);
}
__device__ __forceinline__ void cp16(uint32_t saddr, const void* g) {
    asm volatile("cp.async.cg.shared.global [%0], [%1], 16;\n" :: "r"(saddr), "l"(g));
}
__device__ __forceinline__ void lds128(uint4& v, uint32_t a) {
    asm volatile("ld.shared.v4.u32 {%0,%1,%2,%3}, [%4];"
                 : "=r"(v.x), "=r"(v.y), "=r"(v.z), "=r"(v.w) : "r"(a));
}
__device__ __forceinline__ void mma_f16(float* d, const uint4& a, uint32_t b0, uint32_t b1) {
    asm volatile("mma.sync.aligned.m16n8k16.row.col.f32.f16.f16.f32 "
                 "{%0,%1,%2,%3},{%4,%5,%6,%7},{%8,%9},{%0,%1,%2,%3};"
                 : "+f"(d[0]), "+f"(d[1]), "+f"(d[2]), "+f"(d[3])
                 : "r"(a.x), "r"(a.y), "r"(a.z), "r"(a.w), "r"(b0), "r"(b1));
}

// ---------------------------------------------------------------------------
// Prepass 1: x fp32 -> fp16 A image, fragment-major.
// Block (m16,k16): lane t holds a0..a3 = (r,2c|2c+1),(r+8,..),(r,2c+8|9),(r+8,..)
//   r = t>>2, c = t&3.  16B per lane -> STG.128.
// ---------------------------------------------------------------------------
__global__ void __launch_bounds__(256) halfx_kernel(const float* __restrict__ x) {
    int gid = blockIdx.x * 256 + threadIdx.x;
    int blk = gid >> 5, t = gid & 31;
    int m16 = blk >> 8;              // blk / KB16
    int k16 = blk & (KB16 - 1);
    int r = t >> 2, c = t & 3;
    const float* base = x + (size_t)(m16 * 16 + r) * IN_F + k16 * 16 + 2 * c;
    float2 v00 = *(const float2*)(base);
    float2 v01 = *(const float2*)(base + 8);
    float2 v10 = *(const float2*)(base + (size_t)8 * IN_F);
    float2 v11 = *(const float2*)(base + (size_t)8 * IN_F + 8);
    __half2 h0 = __floats2half2_rn(v00.x, v00.y);
    __half2 h1 = __floats2half2_rn(v10.x, v10.y);
    __half2 h2 = __floats2half2_rn(v01.x, v01.y);
    __half2 h3 = __floats2half2_rn(v11.x, v11.y);
    uint4 o;
    o.x = *(uint32_t*)&h0; o.y = *(uint32_t*)&h1;
    o.z = *(uint32_t*)&h2; o.w = *(uint32_t*)&h3;
    *(uint4*)(g_Ah + (size_t)blk * 512 + t * 16) = o;
}

// ---------------------------------------------------------------------------
// Prepass 2: dequant 4-bit -> fp16 B image, fragment-major.
// Block (n16,k16): lane t holds, for nu0=n16*16+(t>>2) and nu1=nu0+8:
//   b0 = W[k=2c,2c+1][nu], b1 = W[k=2c+8,2c+9][nu]   (c = t&3)
// ---------------------------------------------------------------------------
__global__ void __launch_bounds__(256) dequanth_kernel(const int* __restrict__ qw,
                                                       const int* __restrict__ qz,
                                                       const float* __restrict__ scales) {
    int gid = blockIdx.x * 256 + threadIdx.x;
    int blk = gid >> 5, t = gid & 31;
    int n16 = blk >> 8;              // blk / KB16
    int k16 = blk & (KB16 - 1);
    int c = t & 3;
    int k0 = k16 * 16;
    int g = k0 >> 7;
    int wrow = k0 >> 3;
    uint32_t o[4];
#pragma unroll
    for (int s_ = 0; s_ < 2; s_++) {
        int nu = n16 * 16 + (t >> 2) + s_ * 8;
        float sc = scales[g * OUT_F + nu];
        uint32_t zw = (uint32_t)qz[g * (OUT_F / 8) + (nu >> 3)];
        float nz = -sc * (float)(((zw >> ((nu & 7) * 4)) & 15u) + 1u);
        uint32_t w0 = (uint32_t)qw[(size_t)wrow * OUT_F + nu];
        uint32_t w1 = (uint32_t)qw[(size_t)(wrow + 1) * OUT_F + nu];
        float f0 = fmaf(sc, (float)((w0 >> (8 * c))     & 15u), nz);
        float f1 = fmaf(sc, (float)((w0 >> (8 * c + 4)) & 15u), nz);
        float f2 = fmaf(sc, (float)((w1 >> (8 * c))     & 15u), nz);
        float f3 = fmaf(sc, (float)((w1 >> (8 * c + 4)) & 15u), nz);
        __half2 b0 = __floats2half2_rn(f0, f1);
        __half2 b1 = __floats2half2_rn(f2, f3);
        o[s_ * 2]     = *(uint32_t*)&b0;
        o[s_ * 2 + 1] = *(uint32_t*)&b1;
    }
    uint4 v; v.x = o[0]; v.y = o[1]; v.z = o[2]; v.w = o[3];
    *(uint4*)(g_Bh + (size_t)blk * 512 + t * 16) = v;
}

// ---------------------------------------------------------------------------
// GEMM: out = g_Ah @ g_Bh^T + bias.  CTA 128x256, 512 threads,
// warps 4(m) x 4(n), warp tile 32x64, BK=32, 3-stage cp.async ring.
// ---------------------------------------------------------------------------
#define STG 24576                       // stage: A 8KB + B 16KB
#define SMEM_TOTAL (3 * STG)            // 73728

__global__ void __launch_bounds__(512, 1)
gemm_kernel(const float* __restrict__ bias, float* __restrict__ out) {
    extern __shared__ __align__(16) char smem[];
    const uint32_t sb = smem_u32(smem);
    const int tid  = threadIdx.x;
    const int wid  = tid >> 5;
    const int lane = tid & 31;
    const int wm   = wid & 3;           // m-warp 0..3
    const int wn   = wid >> 2;          // n-warp 0..3
    const int m0   = blockIdx.y * BM;
    const int n0   = blockIdx.x * BN;

    float acc[2][8][4];
#pragma unroll
    for (int mi = 0; mi < 2; mi++)
#pragma unroll
        for (int ni = 0; ni < 8; ni++)
#pragma unroll
            for (int j = 0; j < 4; j++) acc[mi][ni][j] = 0.0f;

    // fill: A 8 m16-blk x 2 k16-blk (512 chunks), B 16 n16-blk x 2 (1024 chunks)
    auto fill = [&](int it) {
        uint32_t st = sb + (uint32_t)(it % 3) * STG;
        int kb = it * 2;
        {
            int mblk = tid >> 6, kblk = (tid >> 5) & 1, ln = tid & 31;
            const uint8_t* src = g_Ah +
                ((size_t)((m0 >> 4) + mblk) * KB16 + kb + kblk) * 512 + ln * 16;
            cp16(st + (uint32_t)(mblk * 2 + kblk) * 512 + ln * 16, src);
        }
#pragma unroll
        for (int j = 0; j < 2; j++) {
            int c2 = tid + 512 * j;
            int nblk = c2 >> 6, kblk = (c2 >> 5) & 1, ln = c2 & 31;
            const uint8_t* src = g_Bh +
                ((size_t)((n0 >> 4) + nblk) * KB16 + kb + kblk) * 512 + ln * 16;
            cp16(st + 8192 + (uint32_t)(nblk * 2 + kblk) * 512 + ln * 16, src);
        }
    };

    fill(0);
    asm volatile("cp.async.commit_group;\n" ::: "memory");
    fill(1);
    asm volatile("cp.async.commit_group;\n" ::: "memory");

    const uint32_t a_off = (uint32_t)lane * 16;

    for (int it = 0; it < NKI; it++) {
        asm volatile("cp.async.wait_group 1;\n" ::: "memory");
        __syncthreads();
        if (it + 2 < NKI) fill(it + 2);
        asm volatile("cp.async.commit_group;\n" ::: "memory");

        const uint32_t st = sb + (uint32_t)(it % 3) * STG;
#pragma unroll
        for (int ks = 0; ks < 2; ks++) {
            uint4 a[2], b[4];
#pragma unroll
            for (int mi = 0; mi < 2; mi++)
                lds128(a[mi], st + (uint32_t)(((wm * 2 + mi) * 2 + ks)) * 512 + a_off);
#pragma unroll
            for (int np = 0; np < 4; np++)
                lds128(b[np], st + 8192 + (uint32_t)(((wn * 4 + np) * 2 + ks)) * 512 + a_off);
#pragma unroll
            for (int mi = 0; mi < 2; mi++)
#pragma unroll
                for (int np = 0; np < 4; np++) {
                    mma_f16(acc[mi][np * 2],     a[mi], b[np].x, b[np].y);
                    mma_f16(acc[mi][np * 2 + 1], a[mi], b[np].z, b[np].w);
                }
        }
    }

    // epilogue: + bias
#pragma unroll
    for (int mi = 0; mi < 2; mi++) {
        int r0 = m0 + wm * 32 + mi * 16 + (lane >> 2);
#pragma unroll
        for (int np = 0; np < 4; np++)
#pragma unroll
            for (int sub = 0; sub < 2; sub++) {
                int c = n0 + wn * 64 + np * 16 + sub * 8 + (lane & 3) * 2;
                const float* d = acc[mi][np * 2 + sub];
                float2 bv = *(const float2*)(bias + c);
                float2 v0, v1;
                v0.x = d[0] + bv.x; v0.y = d[1] + bv.y;
                v1.x = d[2] + bv.x; v1.y = d[3] + bv.y;
                *(float2*)(out + (size_t)r0 * OUT_F + c)       = v0;
                *(float2*)(out + (size_t)(r0 + 8) * OUT_F + c) = v1;
            }
    }
}

// ---------------------------------------------------------------------------
// Launch.  inputs: x, qweight, qzeros, scales, g_idx, bias
// ---------------------------------------------------------------------------
extern "C" void kernel_launch(void* const* d_in, const int* in_sizes, int n_in,
                              void* d_out, int out_size) {
    const float* x       = (const float*)d_in[0];
    const int*   qweight = (const int*)d_in[1];
    const int*   qzeros  = (const int*)d_in[2];
    const float* scales  = (const float*)d_in[3];
    const float* bias    = (const float*)d_in[5];
    float*       out     = (float*)d_out;

    halfx_kernel<<<(TOKENS / 16) * KB16 * 32 / 256, 256>>>(x);
    dequanth_kernel<<<(OUT_F / 16) * KB16 * 32 / 256, 256>>>(qweight, qzeros, scales);

    cudaFuncSetAttribute(gemm_kernel, cudaFuncAttributeMaxDynamicSharedMemorySize,
                         SMEM_TOTAL);
    dim3 grid(OUT_F / BN, TOKENS / BM);
    gemm_kernel<<<grid, 512, SMEM_TOTAL>>>(bias, out);
}

// round 11
// speedup vs baseline: 5.8722x; 1.1754x over previous
#include <cuda_runtime.h>
#include <cuda_fp16.h>
#include <cstdint>

#define IN_F   4096
#define OUT_F  4096
#define TOKENS 8192

#define BM 128
#define BN 256
#define BK 64
#define NKI  (IN_F / BK)    // 64 iterations
#define KB16 (IN_F / 16)    // 256 k16-blocks along K

// fragment-major fp16 images: one 512B block per (16 x 16) tile, lane-major
__device__ __align__(16) uint8_t g_Ah[(size_t)TOKENS * IN_F * 2];  // 64 MB
__device__ __align__(16) uint8_t g_Bh[(size_t)OUT_F * IN_F * 2];   // 32 MB

__device__ __forceinline__ uint32_t smem_u32(const void* p) {
    return (uint32_t)__cvta_generic_to_shared(p);
}
__device__ __forceinline__ void cp16(uint32_t saddr, const void* g) {
    asm volatile("cp.async.cg.shared.global [%0], [%1], 16;\n" :: "r"(saddr), "l"(g));
}
__device__ __forceinline__ void lds128(uint4& v, uint32_t a) {
    asm volatile("ld.shared.v4.u32 {%0,%1,%2,%3}, [%4];"
                 : "=r"(v.x), "=r"(v.y), "=r"(v.z), "=r"(v.w) : "r"(a));
}
__device__ __forceinline__ void mma_f16(float* d, const uint4& a, uint32_t b0, uint32_t b1) {
    asm volatile("mma.sync.aligned.m16n8k16.row.col.f32.f16.f16.f32 "
                 "{%0,%1,%2,%3},{%4,%5,%6,%7},{%8,%9},{%0,%1,%2,%3};"
                 : "+f"(d[0]), "+f"(d[1]), "+f"(d[2]), "+f"(d[3])
                 : "r"(a.x), "r"(a.y), "r"(a.z), "r"(a.w), "r"(b0), "r"(b1));
}

// ---------------------------------------------------------------------------
// Prepass 1: x fp32 -> fp16 A image, fragment-major.
// Block (m16,k16): lane t holds a0..a3 = (r,2c|2c+1),(r+8,..),(r,2c+8|9),(r+8,..)
// ---------------------------------------------------------------------------
__global__ void __launch_bounds__(256) halfx_kernel(const float* __restrict__ x) {
    int gid = blockIdx.x * 256 + threadIdx.x;
    int blk = gid >> 5, t = gid & 31;
    int m16 = blk >> 8;              // blk / KB16
    int k16 = blk & (KB16 - 1);
    int r = t >> 2, c = t & 3;
    const float* base = x + (size_t)(m16 * 16 + r) * IN_F + k16 * 16 + 2 * c;
    float2 v00 = *(const float2*)(base);
    float2 v01 = *(const float2*)(base + 8);
    float2 v10 = *(const float2*)(base + (size_t)8 * IN_F);
    float2 v11 = *(const float2*)(base + (size_t)8 * IN_F + 8);
    __half2 h0 = __floats2half2_rn(v00.x, v00.y);
    __half2 h1 = __floats2half2_rn(v10.x, v10.y);
    __half2 h2 = __floats2half2_rn(v01.x, v01.y);
    __half2 h3 = __floats2half2_rn(v11.x, v11.y);
    uint4 o;
    o.x = *(uint32_t*)&h0; o.y = *(uint32_t*)&h1;
    o.z = *(uint32_t*)&h2; o.w = *(uint32_t*)&h3;
    *(uint4*)(g_Ah + (size_t)blk * 512 + t * 16) = o;
}

// ---------------------------------------------------------------------------
// Prepass 2: dequant 4-bit -> fp16 B image, fragment-major.
// ---------------------------------------------------------------------------
__global__ void __launch_bounds__(256) dequanth_kernel(const int* __restrict__ qw,
                                                       const int* __restrict__ qz,
                                                       const float* __restrict__ scales) {
    int gid = blockIdx.x * 256 + threadIdx.x;
    int blk = gid >> 5, t = gid & 31;
    int n16 = blk >> 8;              // blk / KB16
    int k16 = blk & (KB16 - 1);
    int c = t & 3;
    int k0 = k16 * 16;
    int g = k0 >> 7;
    int wrow = k0 >> 3;
    uint32_t o[4];
#pragma unroll
    for (int s_ = 0; s_ < 2; s_++) {
        int nu = n16 * 16 + (t >> 2) + s_ * 8;
        float sc = scales[g * OUT_F + nu];
        uint32_t zw = (uint32_t)qz[g * (OUT_F / 8) + (nu >> 3)];
        float nz = -sc * (float)(((zw >> ((nu & 7) * 4)) & 15u) + 1u);
        uint32_t w0 = (uint32_t)qw[(size_t)wrow * OUT_F + nu];
        uint32_t w1 = (uint32_t)qw[(size_t)(wrow + 1) * OUT_F + nu];
        float f0 = fmaf(sc, (float)((w0 >> (8 * c))     & 15u), nz);
        float f1 = fmaf(sc, (float)((w0 >> (8 * c + 4)) & 15u), nz);
        float f2 = fmaf(sc, (float)((w1 >> (8 * c))     & 15u), nz);
        float f3 = fmaf(sc, (float)((w1 >> (8 * c + 4)) & 15u), nz);
        __half2 b0 = __floats2half2_rn(f0, f1);
        __half2 b1 = __floats2half2_rn(f2, f3);
        o[s_ * 2]     = *(uint32_t*)&b0;
        o[s_ * 2 + 1] = *(uint32_t*)&b1;
    }
    uint4 v; v.x = o[0]; v.y = o[1]; v.z = o[2]; v.w = o[3];
    *(uint4*)(g_Bh + (size_t)blk * 512 + t * 16) = v;
}

// ---------------------------------------------------------------------------
// GEMM: out = g_Ah @ g_Bh^T + bias.  CTA 128x256, 512 threads,
// warps 4(m) x 4(n), warp tile 32x64, BK=64 (4 k16 steps), 3-stage ring.
// ---------------------------------------------------------------------------
#define STG 49152                       // stage: A 16KB + B 32KB
#define SMEM_TOTAL (3 * STG)            // 147456

__global__ void __launch_bounds__(512, 1)
gemm_kernel(const float* __restrict__ bias, float* __restrict__ out) {
    extern __shared__ __align__(16) char smem[];
    const uint32_t sb = smem_u32(smem);
    const int tid  = threadIdx.x;
    const int wid  = tid >> 5;
    const int lane = tid & 31;
    const int wm   = wid & 3;           // m-warp 0..3
    const int wn   = wid >> 2;          // n-warp 0..3
    const int m0   = blockIdx.y * BM;
    const int n0   = blockIdx.x * BN;

    float acc[2][8][4];
#pragma unroll
    for (int mi = 0; mi < 2; mi++)
#pragma unroll
        for (int ni = 0; ni < 8; ni++)
#pragma unroll
            for (int j = 0; j < 4; j++) acc[mi][ni][j] = 0.0f;

    // fill: A 8 m16-blk x 4 k16-blk (1024 chunks), B 16 n16-blk x 4 (2048 chunks)
    auto fill = [&](int it) {
        uint32_t st = sb + (uint32_t)(it % 3) * STG;
        int kb = it * 4;
#pragma unroll
        for (int j = 0; j < 2; j++) {
            int c2 = tid + 512 * j;
            int blk = c2 >> 5, ln = c2 & 31;
            int mblk = blk >> 2, kblk = blk & 3;
            const uint8_t* src = g_Ah +
                ((size_t)((m0 >> 4) + mblk) * KB16 + kb + kblk) * 512 + ln * 16;
            cp16(st + (uint32_t)blk * 512 + ln * 16, src);
        }
#pragma unroll
        for (int j = 0; j < 4; j++) {
            int c2 = tid + 512 * j;
            int blk = c2 >> 5, ln = c2 & 31;
            int nblk = blk >> 2, kblk = blk & 3;
            const uint8_t* src = g_Bh +
                ((size_t)((n0 >> 4) + nblk) * KB16 + kb + kblk) * 512 + ln * 16;
            cp16(st + 16384 + (uint32_t)blk * 512 + ln * 16, src);
        }
    };

    fill(0);
    asm volatile("cp.async.commit_group;\n" ::: "memory");
    fill(1);
    asm volatile("cp.async.commit_group;\n" ::: "memory");

    const uint32_t f_off = (uint32_t)lane * 16;

    for (int it = 0; it < NKI; it++) {
        asm volatile("cp.async.wait_group 1;\n" ::: "memory");
        __syncthreads();
        if (it + 2 < NKI) fill(it + 2);
        asm volatile("cp.async.commit_group;\n" ::: "memory");

        const uint32_t st = sb + (uint32_t)(it % 3) * STG;
#pragma unroll
        for (int ks = 0; ks < 4; ks++) {
            uint4 a[2], b[4];
#pragma unroll
            for (int mi = 0; mi < 2; mi++)
                lds128(a[mi], st + (uint32_t)(((wm * 2 + mi) * 4 + ks)) * 512 + f_off);
#pragma unroll
            for (int np = 0; np < 4; np++)
                lds128(b[np], st + 16384 + (uint32_t)(((wn * 4 + np) * 4 + ks)) * 512 + f_off);
#pragma unroll
            for (int mi = 0; mi < 2; mi++)
#pragma unroll
                for (int np = 0; np < 4; np++) {
                    mma_f16(acc[mi][np * 2],     a[mi], b[np].x, b[np].y);
                    mma_f16(acc[mi][np * 2 + 1], a[mi], b[np].z, b[np].w);
                }
        }
    }

    // epilogue: + bias
#pragma unroll
    for (int mi = 0; mi < 2; mi++) {
        int r0 = m0 + wm * 32 + mi * 16 + (lane >> 2);
#pragma unroll
        for (int np = 0; np < 4; np++)
#pragma unroll
            for (int sub = 0; sub < 2; sub++) {
                int c = n0 + wn * 64 + np * 16 + sub * 8 + (lane & 3) * 2;
                const float* d = acc[mi][np * 2 + sub];
                float2 bv = *(const float2*)(bias + c);
                float2 v0, v1;
                v0.x = d[0] + bv.x; v0.y = d[1] + bv.y;
                v1.x = d[2] + bv.x; v1.y = d[3] + bv.y;
                *(float2*)(out + (size_t)r0 * OUT_F + c)       = v0;
                *(float2*)(out + (size_t)(r0 + 8) * OUT_F + c) = v1;
            }
    }
}

// ---------------------------------------------------------------------------
// Launch.  inputs: x, qweight, qzeros, scales, g_idx, bias
// ---------------------------------------------------------------------------
extern "C" void kernel_launch(void* const* d_in, const int* in_sizes, int n_in,
                              void* d_out, int out_size) {
    const float* x       = (const float*)d_in[0];
    const int*   qweight = (const int*)d_in[1];
    const int*   qzeros  = (const int*)d_in[2];
    const float* scales  = (const float*)d_in[3];
    const float* bias    = (const float*)d_in[5];
    float*       out     = (float*)d_out;

    halfx_kernel<<<(TOKENS / 16) * KB16 * 32 / 256, 256>>>(x);
    dequanth_kernel<<<(OUT_F / 16) * KB16 * 32 / 256, 256>>>(qweight, qzeros, scales);

    cudaFuncSetAttribute(gemm_kernel, cudaFuncAttributeMaxDynamicSharedMemorySize,
                         SMEM_TOTAL);
    dim3 grid(OUT_F / BN, TOKENS / BM);
    gemm_kernel<<<grid, 512, SMEM_TOTAL>>>(bias, out);
}